// round 12
// baseline (speedup 1.0000x reference)
#include <cuda_runtime.h>
#include <math.h>
#include <float.h>

#define BATCH  2
#define SEQ    2048
#define DMODEL 1024
#define NHEAD  16
#define DHEAD  64
#define TOPK   32

// ---------------- device scratch ----------------
__device__ float g_q[(size_t)BATCH * SEQ * DMODEL];
__device__ float g_k[(size_t)BATCH * SEQ * DMODEL];
__device__ float g_v[(size_t)BATCH * SEQ * DMODEL];
__device__ float g_ctx[(size_t)BATCH * SEQ * DMODEL];
__device__ float g_s[(size_t)BATCH * NHEAD * SEQ * SEQ];  // 536 MB score scratch

// =======================================================================================
// Projection kernel v3 (verbatim R9, proven 47 TF/s). Q, K, V via blockIdx.z.
// 128x128 tile, 256 thr, 8x8 microtile, double-buffered, 1 barrier/slab, 1 CTA/SM.
// Per-output FFMA sequence BITWISE IDENTICAL to R2/R4/R5/R9.
// =======================================================================================
__global__ __launch_bounds__(256, 1) void proj_kernel(
    const float* __restrict__ query, const float* __restrict__ key,
    const float* __restrict__ value,
    const float* __restrict__ Wq, const float* __restrict__ bq,
    const float* __restrict__ Wk, const float* __restrict__ bk,
    const float* __restrict__ Wv, const float* __restrict__ bv)
{
    __shared__ float As[2][16][132];
    __shared__ float Ws[2][16][132];

    const int z = blockIdx.z;
    const float* A    = (z == 0) ? query : (z == 1) ? key : value;
    const float* W    = (z == 0) ? Wq    : (z == 1) ? Wk  : Wv;
    const float* bias = (z == 0) ? bq    : (z == 1) ? bk  : bv;
    float*       C    = (z == 0) ? g_q   : (z == 1) ? g_k : g_v;

    const int tid = threadIdx.x;          // 0..255
    const int m0 = blockIdx.y * 128;
    const int n0 = blockIdx.x * 128;
    const int tr = tid >> 4;
    const int tc = tid & 15;

    const int r0 = tid >> 1;              // 0..127
    const int c0 = (tid & 1) << 3;        // 0 or 8

    const float* Arow = A + (size_t)(m0 + r0) * 1024 + c0;
    const float* Wrow = W + (size_t)(n0 + r0) * 1024 + c0;

    {
        float4 a0 = *(const float4*)(Arow);
        float4 a1 = *(const float4*)(Arow + 4);
        As[0][c0 + 0][r0] = a0.x; As[0][c0 + 1][r0] = a0.y;
        As[0][c0 + 2][r0] = a0.z; As[0][c0 + 3][r0] = a0.w;
        As[0][c0 + 4][r0] = a1.x; As[0][c0 + 5][r0] = a1.y;
        As[0][c0 + 6][r0] = a1.z; As[0][c0 + 7][r0] = a1.w;
        float4 w0 = *(const float4*)(Wrow);
        float4 w1 = *(const float4*)(Wrow + 4);
        Ws[0][c0 + 0][r0] = w0.x; Ws[0][c0 + 1][r0] = w0.y;
        Ws[0][c0 + 2][r0] = w0.z; Ws[0][c0 + 3][r0] = w0.w;
        Ws[0][c0 + 4][r0] = w1.x; Ws[0][c0 + 5][r0] = w1.y;
        Ws[0][c0 + 6][r0] = w1.z; Ws[0][c0 + 7][r0] = w1.w;
    }
    __syncthreads();

    float acc[8][8], p[8][8];
#pragma unroll
    for (int i = 0; i < 8; i++)
#pragma unroll
        for (int j = 0; j < 8; j++) acc[i][j] = 0.f;

#pragma unroll 1
    for (int s = 0; s < 64; s++) {
        const int cur = s & 1;
        float4 na0, na1, nw0, nw1;
        if (s < 63) {
            na0 = *(const float4*)(Arow + (size_t)(s + 1) * 16);
            na1 = *(const float4*)(Arow + (size_t)(s + 1) * 16 + 4);
            nw0 = *(const float4*)(Wrow + (size_t)(s + 1) * 16);
            nw1 = *(const float4*)(Wrow + (size_t)(s + 1) * 16 + 4);
        }
        const bool pinit = ((s & 3) == 0);
#pragma unroll
        for (int kk = 0; kk < 16; kk++) {
            float a[8], w[8];
            *(float4*)(a)     = *(const float4*)&As[cur][kk][tr * 8];
            *(float4*)(a + 4) = *(const float4*)&As[cur][kk][tr * 8 + 4];
            *(float4*)(w)     = *(const float4*)&Ws[cur][kk][tc * 8];
            *(float4*)(w + 4) = *(const float4*)&Ws[cur][kk][tc * 8 + 4];
            if (pinit && kk == 0) {
#pragma unroll
                for (int i = 0; i < 8; i++)
#pragma unroll
                    for (int j = 0; j < 8; j++) p[i][j] = a[i] * w[j];
            } else {
#pragma unroll
                for (int i = 0; i < 8; i++)
#pragma unroll
                    for (int j = 0; j < 8; j++) p[i][j] += a[i] * w[j];
            }
        }
        if ((s & 3) == 3) {
#pragma unroll
            for (int i = 0; i < 8; i++)
#pragma unroll
                for (int j = 0; j < 8; j++) acc[i][j] += p[i][j];
        }
        if (s < 63) {
            const int nxt = cur ^ 1;
            As[nxt][c0 + 0][r0] = na0.x; As[nxt][c0 + 1][r0] = na0.y;
            As[nxt][c0 + 2][r0] = na0.z; As[nxt][c0 + 3][r0] = na0.w;
            As[nxt][c0 + 4][r0] = na1.x; As[nxt][c0 + 5][r0] = na1.y;
            As[nxt][c0 + 6][r0] = na1.z; As[nxt][c0 + 7][r0] = na1.w;
            Ws[nxt][c0 + 0][r0] = nw0.x; Ws[nxt][c0 + 1][r0] = nw0.y;
            Ws[nxt][c0 + 2][r0] = nw0.z; Ws[nxt][c0 + 3][r0] = nw0.w;
            Ws[nxt][c0 + 4][r0] = nw1.x; Ws[nxt][c0 + 5][r0] = nw1.y;
            Ws[nxt][c0 + 6][r0] = nw1.z; Ws[nxt][c0 + 7][r0] = nw1.w;
        }
        __syncthreads();
    }

    float bb[8];
#pragma unroll
    for (int j = 0; j < 8; j++) bb[j] = bias[n0 + tc * 8 + j];
#pragma unroll
    for (int i = 0; i < 8; i++) {
        float4 o0, o1;
        o0.x = acc[i][0] + bb[0]; o0.y = acc[i][1] + bb[1];
        o0.z = acc[i][2] + bb[2]; o0.w = acc[i][3] + bb[3];
        o1.x = acc[i][4] + bb[4]; o1.y = acc[i][5] + bb[5];
        o1.z = acc[i][6] + bb[6]; o1.w = acc[i][7] + bb[7];
        float* crow = C + (size_t)(m0 + tr * 8 + i) * 1024 + n0 + tc * 8;
        *(float4*)crow       = o0;
        *(float4*)(crow + 4) = o1;
    }
}

// =======================================================================================
// Scores kernel v2: per (b,h), 128x256 tile of Q*K^T*0.125. 256 thr, 8x16 microtile
// (0.75 B/FLOP -> ~50+ TF/s crossbar cap), 1 CTA/SM (reg-bound; no barriers in the
// main loop so co-residency is unnecessary). K=64 staged ONCE -> 1 barrier.
// Per-output k order: ascending 0..63, init at k==0 — bitwise identical to R5/R9.
// =======================================================================================
__global__ __launch_bounds__(256, 1) void scores_gemm_kernel()
{
    extern __shared__ float sm[];
    float (*Qs)[132] = (float(*)[132])sm;               // [64][132]
    float (*Ks)[264] = (float(*)[264])(sm + 64 * 132);  // [64][264]

    const int z = blockIdx.z;        // b*NHEAD + h
    const int b = z >> 4;
    const int h = z & 15;
    const int tid = threadIdx.x;     // 0..255
    const int m0 = blockIdx.y * 128;
    const int n0 = blockIdx.x * 256;
    const int tr = tid >> 4;         // 0..15 -> rows tr*8..+7
    const int tc = tid & 15;         // 0..15 -> cols tc*16..+15

    // stage Q tile [128 x 64] (2 threads/row), k-major
    {
        const int r    = tid >> 1;           // 0..127
        const int half = (tid & 1) << 5;     // 0 or 32
        const float* Qrow = g_q + (size_t)(b * SEQ + m0 + r) * DMODEL + h * DHEAD + half;
#pragma unroll
        for (int i = 0; i < 8; i++) {
            float4 qv = *(const float4*)(Qrow + i * 4);
            const int kc = half + i * 4;
            Qs[kc + 0][r] = qv.x; Qs[kc + 1][r] = qv.y;
            Qs[kc + 2][r] = qv.z; Qs[kc + 3][r] = qv.w;
        }
    }
    // stage K tile [256 x 64] (1 thread/row), k-major
    {
        const float* Krow = g_k + (size_t)(b * SEQ + n0 + tid) * DMODEL + h * DHEAD;
#pragma unroll
        for (int i = 0; i < 16; i++) {
            float4 kv = *(const float4*)(Krow + i * 4);
            const int kc = i * 4;
            Ks[kc + 0][tid] = kv.x; Ks[kc + 1][tid] = kv.y;
            Ks[kc + 2][tid] = kv.z; Ks[kc + 3][tid] = kv.w;
        }
    }
    __syncthreads();

    float acc[8][16];
#pragma unroll 4
    for (int kk = 0; kk < 64; kk++) {
        float a[8], w[16];
        *(float4*)(a)      = *(const float4*)&Qs[kk][tr * 8];
        *(float4*)(a + 4)  = *(const float4*)&Qs[kk][tr * 8 + 4];
        *(float4*)(w)      = *(const float4*)&Ks[kk][tc * 16];
        *(float4*)(w + 4)  = *(const float4*)&Ks[kk][tc * 16 + 4];
        *(float4*)(w + 8)  = *(const float4*)&Ks[kk][tc * 16 + 8];
        *(float4*)(w + 12) = *(const float4*)&Ks[kk][tc * 16 + 12];
        if (kk == 0) {
#pragma unroll
            for (int i = 0; i < 8; i++)
#pragma unroll
                for (int j = 0; j < 16; j++) acc[i][j] = a[i] * w[j];
        } else {
#pragma unroll
            for (int i = 0; i < 8; i++)
#pragma unroll
                for (int j = 0; j < 16; j++) acc[i][j] += a[i] * w[j];
        }
    }

    float* Cz = g_s + (size_t)z * SEQ * SEQ;
#pragma unroll
    for (int i = 0; i < 8; i++) {
        float* crow = Cz + (size_t)(m0 + tr * 8 + i) * SEQ + n0 + tc * 16;
#pragma unroll
        for (int v4 = 0; v4 < 4; v4++) {
            float4 o;
            o.x = acc[i][v4 * 4 + 0] * 0.125f;
            o.y = acc[i][v4 * 4 + 1] * 0.125f;
            o.z = acc[i][v4 * 4 + 2] * 0.125f;
            o.w = acc[i][v4 * 4 + 3] * 0.125f;
            *(float4*)(crow + v4 * 4) = o;
        }
    }
}

// =======================================================================================
// FAST fp32 NT GEMM (verbatim R5/R9) — output projection only.
// =======================================================================================
__global__ __launch_bounds__(256, 2) void out_gemm_kernel(
    float* __restrict__ C, const float* __restrict__ W, const float* __restrict__ bias)
{
    __shared__ float As[16][132];
    __shared__ float Ws[16][132];
    const float* A = g_ctx;
    const int tid = threadIdx.x;
    const int m0 = blockIdx.y * 128;
    const int n0 = blockIdx.x * 128;
    const int tr = tid >> 4;
    const int tc = tid & 15;
    float acc[8][8];
#pragma unroll
    for (int i = 0; i < 8; i++)
#pragma unroll
        for (int j = 0; j < 8; j++) acc[i][j] = 0.f;

    const int r0 = tid >> 2;
    const int c0 = (tid & 3) << 2;

    for (int k0 = 0; k0 < 1024; k0 += 16) {
#pragma unroll
        for (int t = 0; t < 2; t++) {
            int r = r0 + t * 64;
            float4 av = *(const float4*)(A + (size_t)(m0 + r) * 1024 + k0 + c0);
            As[c0 + 0][r] = av.x; As[c0 + 1][r] = av.y;
            As[c0 + 2][r] = av.z; As[c0 + 3][r] = av.w;
            float4 wv = *(const float4*)(W + (size_t)(n0 + r) * 1024 + k0 + c0);
            Ws[c0 + 0][r] = wv.x; Ws[c0 + 1][r] = wv.y;
            Ws[c0 + 2][r] = wv.z; Ws[c0 + 3][r] = wv.w;
        }
        __syncthreads();
#pragma unroll
        for (int k = 0; k < 16; k++) {
            float a[8], w[8];
            *(float4*)(a)     = *(const float4*)&As[k][tr * 8];
            *(float4*)(a + 4) = *(const float4*)&As[k][tr * 8 + 4];
            *(float4*)(w)     = *(const float4*)&Ws[k][tc * 8];
            *(float4*)(w + 4) = *(const float4*)&Ws[k][tc * 8 + 4];
#pragma unroll
            for (int i = 0; i < 8; i++)
#pragma unroll
                for (int j = 0; j < 8; j++)
                    acc[i][j] += a[i] * w[j];
        }
        __syncthreads();
    }

    float bb[8];
#pragma unroll
    for (int j = 0; j < 8; j++) bb[j] = bias[n0 + tc * 8 + j];
#pragma unroll
    for (int i = 0; i < 8; i++) {
        float4 o0, o1;
        o0.x = acc[i][0] + bb[0]; o0.y = acc[i][1] + bb[1];
        o0.z = acc[i][2] + bb[2]; o0.w = acc[i][3] + bb[3];
        o1.x = acc[i][4] + bb[4]; o1.y = acc[i][5] + bb[5];
        o1.z = acc[i][6] + bb[6]; o1.w = acc[i][7] + bb[7];
        float* crow = C + (size_t)(m0 + tr * 8 + i) * 1024 + n0 + tc * 8;
        *(float4*)crow       = o0;
        *(float4*)(crow + 4) = o1;
    }
}

// ---------------- top-k(32) + softmax + V gather; vectorized row loader ----------------
// Only the GMEM->SMEM loader changed vs R5/R9 (float4/int4, 4x fewer LDGs, higher MLP);
// SMEM contents and everything downstream are byte-identical.
__global__ __launch_bounds__(128) void topk_attn_kernel(const int* __restrict__ mask)
{
    __shared__ float sv[4][SEQ];
    __shared__ float selv[4][TOPK];
    __shared__ int   seli[4][TOPK];

    const int warp = threadIdx.x >> 5;
    const int lane = threadIdx.x & 31;
    const int rid = blockIdx.x * 4 + warp;     // (b*SEQ + q)*NHEAD + h
    const int h  = rid & 15;
    const int bq = rid >> 4;
    const int q  = bq & (SEQ - 1);
    const int b  = bq >> 11;

    const float* srow = g_s + ((size_t)(b * NHEAD + h) * SEQ + q) * SEQ;
    const int*   mrow = mask + ((size_t)b * SEQ + q) * SEQ;
    float* svw = sv[warp];

#pragma unroll 4
    for (int j0 = lane * 4; j0 < SEQ; j0 += 128) {
        float4 s = *(const float4*)(srow + j0);
        int4   m = *(const int4*)(mrow + j0);
        if (m.x == 0) s.x = -1e9f;
        if (m.y == 0) s.y = -1e9f;
        if (m.z == 0) s.z = -1e9f;
        if (m.w == 0) s.w = -1e9f;
        *(float4*)&svw[j0] = s;
    }
    __syncwarp();

    float mv = -INFINITY; int mi = 0x7fffffff;
    const int base = lane << 6;
#pragma unroll 8
    for (int j0 = 0; j0 < 64; j0++) {
        int j = base + ((j0 + lane) & 63);
        float v = svw[j];
        if (v > mv || (v == mv && j < mi)) { mv = v; mi = j; }
    }

    for (int it = 0; it < TOPK; it++) {
        float bv = mv; int bi = mi;
#pragma unroll
        for (int off = 16; off; off >>= 1) {
            float ov = __shfl_xor_sync(0xffffffffu, bv, off);
            int   oi = __shfl_xor_sync(0xffffffffu, bi, off);
            if (ov > bv || (ov == bv && oi < bi)) { bv = ov; bi = oi; }
        }
        if (lane == 0) {
            selv[warp][it] = bv;
            seli[warp][it] = bi;
            svw[bi] = -INFINITY;
        }
        const int owner = bi >> 6;
        __syncwarp();
        const int i0 = (owner << 6) + (lane << 1);
        float2 c = *(const float2*)&svw[i0];
        float nv; int ni;
        if (c.x >= c.y) { nv = c.x; ni = i0; } else { nv = c.y; ni = i0 + 1; }
#pragma unroll
        for (int off = 16; off; off >>= 1) {
            float ov = __shfl_xor_sync(0xffffffffu, nv, off);
            int   oi = __shfl_xor_sync(0xffffffffu, ni, off);
            if (ov > nv || (ov == nv && oi < ni)) { nv = ov; ni = oi; }
        }
        if (lane == owner) { mv = nv; mi = ni; }
    }
    __syncwarp();

    const float vsel = selv[warp][lane];
    const float vmax = selv[warp][0];
    float e = expf(vsel - vmax);
    float ssum = e;
#pragma unroll
    for (int off = 16; off; off >>= 1) ssum += __shfl_xor_sync(0xffffffffu, ssum, off);
    const float p = e / ssum;

    const float* vb = g_v + (size_t)b * SEQ * DMODEL + h * DHEAD;
    float acc0 = 0.f, acc1 = 0.f;
#pragma unroll 4
    for (int j = 0; j < TOPK; j++) {
        float pj = __shfl_sync(0xffffffffu, p, j);
        int idx = seli[warp][j];
        const float* vr = vb + (size_t)idx * DMODEL;
        acc0 += pj * vr[lane];
        acc1 += pj * vr[lane + 32];
    }
    float* crow = g_ctx + ((size_t)(b * SEQ + q)) * DMODEL + h * DHEAD;
    crow[lane]      = acc0;
    crow[lane + 32] = acc1;
}

// ---------------- launch ----------------
extern "C" void kernel_launch(void* const* d_in, const int* in_sizes, int n_in,
                              void* d_out, int out_size)
{
    const float* query = (const float*)d_in[0];
    const float* key   = (const float*)d_in[1];
    const float* value = (const float*)d_in[2];
    const float* Wq    = (const float*)d_in[3];
    const float* bq    = (const float*)d_in[4];
    const float* Wk    = (const float*)d_in[5];
    const float* bk    = (const float*)d_in[6];
    const float* Wv    = (const float*)d_in[7];
    const float* bv    = (const float*)d_in[8];
    const float* Wo    = (const float*)d_in[9];
    const float* bo    = (const float*)d_in[10];
    const int*   mask  = (const int*)d_in[11];
    (void)in_sizes; (void)n_in; (void)out_size;

    const int smem_scores = (64 * 132 + 64 * 264) * sizeof(float);  // 101,376 B
    cudaFuncSetAttribute(scores_gemm_kernel,
                         cudaFuncAttributeMaxDynamicSharedMemorySize, smem_scores);

    dim3 gp(DMODEL / 128, (BATCH * SEQ) / 128, 3);         // (8, 32, 3)
    proj_kernel<<<gp, 256>>>(query, key, value, Wq, bq, Wk, bk, Wv, bv);

    dim3 gs(SEQ / 256, SEQ / 128, BATCH * NHEAD);          // (8, 16, 32)
    scores_gemm_kernel<<<gs, 256, smem_scores>>>();

    topk_attn_kernel<<<(BATCH * SEQ * NHEAD) / 4, 128>>>(mask);

    dim3 go(DMODEL / 128, (BATCH * SEQ) / 128);            // (8, 32)
    out_gemm_kernel<<<go, 256>>>((float*)d_out, Wo, bo);
}